// round 2
// baseline (speedup 1.0000x reference)
#include <cuda_runtime.h>
#include <cuda_bf16.h>

// ============================================================================
// EmbeddingDropout: out[b,s,:] = dropout(weight, p=0.1, jax key 42)[words[b,s], :]
//
// Mask reproduction: jax threefry2x32, partitionable counter mode (default in
// modern JAX). For flat table index f (< 2^32):
//   (o0, o1) = threefry2x32(key=(0,42), x0 = hi(f)=0, x1 = lo(f)=f)
//   bits = o0 ^ o1
//   keep  <=>  uniform = (bits>>9)*2^-23 < 0.9f  <=>  bits < 0xE6666600u
//   out = keep ? w * (1/0.9) : 0
// ============================================================================

#define KEEP_THRESH 0xE6666600u   // 7549747 << 9  (7549747*2^-23 == 0.9f exactly)
#define D_COLS      1024

__device__ int g_words_i64;  // 1 if index buffer is int64-laid-out, else int32

// Detect int64 vs int32 layout of the word-index buffer: for little-endian
// int64 values in [0, 50257), every odd 32-bit lane is 0. For int32 data the
// odd lanes are random vocab ids; P(32 consecutive odd lanes all zero) ~ 0.
__global__ void detect_idx_kernel(const unsigned int* __restrict__ w) {
    if (threadIdx.x == 0) {
        int is64 = 1;
#pragma unroll
        for (int i = 1; i < 64; i += 2) is64 &= (w[i] == 0u);
        g_words_i64 = is64;
    }
}

__device__ __forceinline__ unsigned int rotl32(unsigned int x, int r) {
    return __funnelshift_l(x, x, r);   // single SHF.L.W
}

// Threefry-2x32, key (0, 42), input block (0, ctr); returns o0 ^ o1.
__device__ __forceinline__ unsigned int tf_bits(unsigned int ctr) {
    const unsigned int ks1 = 42u;
    const unsigned int ks2 = 0x1BD11BF0u;  // 0 ^ 42 ^ 0x1BD11BDA
    unsigned int x0 = 0u;                  // 0 + ks0(=0)
    unsigned int x1 = ctr + ks1;

#define TF_ROUND(r) { x0 += x1; x1 = rotl32(x1, (r)) ^ x0; }
    TF_ROUND(13) TF_ROUND(15) TF_ROUND(26) TF_ROUND(6)
    x0 += ks1;  x1 += ks2 + 1u;
    TF_ROUND(17) TF_ROUND(29) TF_ROUND(16) TF_ROUND(24)
    x0 += ks2;  x1 += 0u  + 2u;
    TF_ROUND(13) TF_ROUND(15) TF_ROUND(26) TF_ROUND(6)
    x0 += 0u;   x1 += ks1 + 3u;
    TF_ROUND(17) TF_ROUND(29) TF_ROUND(16) TF_ROUND(24)
    x0 += ks1;  x1 += ks2 + 4u;
    TF_ROUND(13) TF_ROUND(15) TF_ROUND(26) TF_ROUND(6)
    x0 += ks2;  x1 += 0u  + 5u;
#undef TF_ROUND
    return x0 ^ x1;
}

__global__ __launch_bounds__(256, 1)
void EmbeddingDropout_15152644620959_kernel(
    const void* __restrict__ words,
    const float* __restrict__ weight,
    float* __restrict__ out)
{
    const int row = blockIdx.x;            // flat (b, s) index
    const int tid = threadIdx.x;           // 256 threads, 4 cols each -> 1024

    // Broadcast load of this row's vocab id (all lanes hit same address).
    unsigned int word;
    if (g_words_i64) {
        word = (unsigned int)__ldg((const long long*)words + row);
    } else {
        word = (unsigned int)__ldg((const int*)words + row);
    }

    const unsigned int c0    = (unsigned int)tid * 4u;
    const unsigned int fbase = word * (unsigned int)D_COLS + c0;

    const float4 w4 = __ldg((const float4*)(weight + (size_t)word * D_COLS + c0));

    // Four independent Threefry evals -> good ILP on the alu/fma pipes.
    const unsigned int b0 = tf_bits(fbase + 0u);
    const unsigned int b1 = tf_bits(fbase + 1u);
    const unsigned int b2 = tf_bits(fbase + 2u);
    const unsigned int b3 = tf_bits(fbase + 3u);

    const float inv_keep = 1.0f / 0.9f;
    float4 o;
    o.x = (b0 < KEEP_THRESH) ? w4.x * inv_keep : 0.0f;
    o.y = (b1 < KEEP_THRESH) ? w4.y * inv_keep : 0.0f;
    o.z = (b2 < KEEP_THRESH) ? w4.z * inv_keep : 0.0f;
    o.w = (b3 < KEEP_THRESH) ? w4.w * inv_keep : 0.0f;

    *(float4*)(out + (size_t)row * D_COLS + c0) = o;
}

extern "C" void kernel_launch(void* const* d_in, const int* in_sizes, int n_in,
                              void* d_out, int out_size) {
    const void*  words  = d_in[0];                 // int32 or int64 vocab ids
    const float* weight = (const float*)d_in[1];   // [50257, 1024] f32
    float*       out    = (float*)d_out;           // [B*S, 1024] f32

    const int rows = out_size / D_COLS;            // 16384

    detect_idx_kernel<<<1, 32>>>((const unsigned int*)words);
    EmbeddingDropout_15152644620959_kernel<<<rows, 256>>>(words, weight, out);
}